// round 3
// baseline (speedup 1.0000x reference)
#include <cuda_runtime.h>

// Fused 1-level DWT (analysis lowpass, stride 2, symmetric pad) + synthesis
// lowpass (transposed conv, dilation 2). 64 rows of length 524288.
//
//   cA[m]    = sum_i H[i] * sig_mir(2m + i - 8)
//   ya[2u]   = sum_r H[8-2r] * cA[u+r]
//   ya[2u+1] = sum_r H[9-2r] * cA[u+r]
// mirror: q<0 -> -1-q ; q>=L -> 2L-1-q.
//
// R3: halo exchange via warp shuffle. One coalesced LDG.128 per thread
// (4 outputs), neighbor float4s (+-1,+-2) via SHFL; 4 edge lanes patch with
// predicated loads. L1 sees only 1 coalesced read + 1 coalesced write.

#define THREADS 256

__constant__ float H[10] = {
    0.160102397974125f,     0.6038292697974729f,
    0.7243085284385744f,    0.13842814590110342f,
   -0.24229488706619015f,  -0.03224486958502952f,
    0.07757149384006515f,  -0.006241490213011705f,
   -0.012580751999015526f,  0.003335725285001549f
};

__device__ __forceinline__ float4 shfl_up4(float4 v, int d) {
    float4 r;
    r.x = __shfl_up_sync(0xFFFFFFFFu, v.x, d);
    r.y = __shfl_up_sync(0xFFFFFFFFu, v.y, d);
    r.z = __shfl_up_sync(0xFFFFFFFFu, v.z, d);
    r.w = __shfl_up_sync(0xFFFFFFFFu, v.w, d);
    return r;
}
__device__ __forceinline__ float4 shfl_dn4(float4 v, int d) {
    float4 r;
    r.x = __shfl_down_sync(0xFFFFFFFFu, v.x, d);
    r.y = __shfl_down_sync(0xFFFFFFFFu, v.y, d);
    r.z = __shfl_down_sync(0xFFFFFFFFu, v.z, d);
    r.w = __shfl_down_sync(0xFFFFFFFFu, v.w, d);
    return r;
}

__global__ __launch_bounds__(THREADS)
void wavelet_shfl_kernel(const float* __restrict__ x,
                         float* __restrict__ y,
                         int Lf4, int blocksPerRow)
{
    const int blk = blockIdx.x;
    const int row = blockIdx.y;
    const long long rowbase = (long long)row * (long long)Lf4 * 4LL;
    const float* xr = x + rowbase;

    const int gf = blk * THREADS + threadIdx.x;   // float4 index within row
    const int lane = threadIdx.x & 31;

    float xv[20];  // sig[4gf-8 .. 4gf+11]

    if (blk == 0 || blk == blocksPerRow - 1) {
        // boundary blocks: scalar mirrored loads (128 of 32768 blocks)
        const int L = Lf4 * 4;
        const int t0 = gf * 4;
        #pragma unroll
        for (int i = 0; i < 20; i++) {
            int q = t0 - 8 + i;
            if (q < 0)        q = -1 - q;
            else if (q >= L)  q = 2 * L - 1 - q;
            xv[i] = xr[q];
        }
    } else {
        const float4* xf4 = reinterpret_cast<const float4*>(xr);
        float4 own = xf4[gf];                    // fully coalesced

        float4 m2 = shfl_up4(own, 2);
        float4 m1 = shfl_up4(own, 1);
        float4 p1 = shfl_dn4(own, 1);
        float4 p2 = shfl_dn4(own, 2);

        // warp-edge patches (interior blocks: indices always in-row)
        if (lane < 2)  m2 = xf4[gf - 2];
        if (lane < 1)  m1 = xf4[gf - 1];
        if (lane > 30) p1 = xf4[gf + 1];
        if (lane > 29) p2 = xf4[gf + 2];

        xv[0]=m2.x;  xv[1]=m2.y;  xv[2]=m2.z;  xv[3]=m2.w;
        xv[4]=m1.x;  xv[5]=m1.y;  xv[6]=m1.z;  xv[7]=m1.w;
        xv[8]=own.x; xv[9]=own.y; xv[10]=own.z; xv[11]=own.w;
        xv[12]=p1.x; xv[13]=p1.y; xv[14]=p1.z; xv[15]=p1.w;
        xv[16]=p2.x; xv[17]=p2.y; xv[18]=p2.z; xv[19]=p2.w;
    }

    // stage 1: 6 approximation coefficients cA[2gf + r], r = 0..5
    float cA[6];
    #pragma unroll
    for (int r = 0; r < 6; r++) {
        float a = 0.0f;
        #pragma unroll
        for (int i = 0; i < 10; i++) {
            a = fmaf(H[i], xv[2*r + i], a);
        }
        cA[r] = a;
    }

    // stage 2: 4 outputs (2 even/odd pairs)
    float o[4];
    #pragma unroll
    for (int s = 0; s < 2; s++) {
        float e = 0.0f, od = 0.0f;
        #pragma unroll
        for (int rp = 0; rp < 5; rp++) {
            e  = fmaf(H[8 - 2*rp], cA[s + rp], e);
            od = fmaf(H[9 - 2*rp], cA[s + rp], od);
        }
        o[2*s + 0] = e;
        o[2*s + 1] = od;
    }

    float4* yo = reinterpret_cast<float4*>(y + rowbase);
    yo[gf] = make_float4(o[0], o[1], o[2], o[3]);
}

extern "C" void kernel_launch(void* const* d_in, const int* in_sizes, int n_in,
                              void* d_out, int out_size)
{
    const float* x = (const float*)d_in[0];
    float* y = (float*)d_out;

    const int B = 64;
    const int total = in_sizes[0];          // 64 * 128 * 4096
    const int L = total / B;                // 524288
    const int Lf4 = L / 4;                  // 131072
    const int blocksPerRow = Lf4 / THREADS; // 512

    dim3 grid(blocksPerRow, B);
    wavelet_shfl_kernel<<<grid, THREADS>>>(x, y, Lf4, blocksPerRow);
}

// round 4
// speedup vs baseline: 1.2210x; 1.2210x over previous
#include <cuda_runtime.h>

// Fused 1-level DWT (analysis lowpass, stride 2, symmetric pad) + synthesis
// lowpass (transposed conv, dilation 2). 64 rows of length 524288.
//
//   cA[m]    = sum_i H[i] * sig_mir(2m + i - 8)
//   ya[2u]   = sum_r H[8-2r] * cA[u+r]
//   ya[2u+1] = sum_r H[9-2r] * cA[u+r]
// mirror: q<0 -> -1-q ; q>=L -> 2L-1-q.
//
// R4: even/odd-split shared memory. Input float4s are deinterleaved by index
// parity into sE / sO. A thread's 24-float window (float4s 2i-2..2i+3) is then
// sE[i-1..i+1], sO[i-1..i+1]: lane-stride-1 LDS.128 -> conflict-free, dense.
// Coalesced LDG; sO offset chosen so sE/sO occupy disjoint bank halves per
// phase during the deinterleaving STS.

#define THREADS  256
#define TILE4    512              // float4s of output per block (2048 floats)
#define WIN4     (TILE4 + 4)      // window float4s: [F0-2, F0+TILE4+2)
#define SE_STRIDE 260             // sE float4 slots (258 used + 2 pad)
                                  // -> sO starts at byte 4160 (== 64 mod 128)

__global__ __launch_bounds__(THREADS)
void wavelet_eo_kernel(const float* __restrict__ x,
                       float* __restrict__ y,
                       int Lf4, int blocksPerRow)
{
    __shared__ float4 sbuf[SE_STRIDE + 258];
    float4* sE = sbuf;              // global float4s with even index
    float4* sO = sbuf + SE_STRIDE;  // odd index

    const int blk = blockIdx.x;
    const int row = blockIdx.y;
    const long long rowbase = (long long)row * (long long)Lf4 * 4LL;
    const float* xr = x + rowbase;
    const int F0 = blk * TILE4;     // first output float4 index (even)
    const int tid = threadIdx.x;

    // ---- stage window float4s [F0-2, F0+TILE4+2) into split smem ----
    if (blk == 0 || blk == blocksPerRow - 1) {
        const int L = Lf4 * 4;
        for (int l = tid; l < WIN4; l += THREADS) {
            const int g4 = F0 - 2 + l;           // global float4 index
            float v[4];
            #pragma unroll
            for (int c = 0; c < 4; c++) {
                int q = g4 * 4 + c;
                if (q < 0)        q = -1 - q;
                else if (q >= L)  q = 2 * L - 1 - q;
                v[c] = xr[q];
            }
            float4 f4 = make_float4(v[0], v[1], v[2], v[3]);
            if (l & 1) sO[l >> 1] = f4; else sE[l >> 1] = f4;
        }
    } else {
        const float4* xf4 = reinterpret_cast<const float4*>(xr) + (F0 - 2);
        #pragma unroll
        for (int p = 0; p < 2; p++) {
            const int l = tid + p * THREADS;
            float4 f4 = xf4[l];                  // coalesced
            if (l & 1) sO[l >> 1] = f4; else sE[l >> 1] = f4;
        }
        if (tid < 4) {
            const int l = tid + 2 * THREADS;
            float4 f4 = xf4[l];
            if (l & 1) sO[l >> 1] = f4; else sE[l >> 1] = f4;
        }
    }
    __syncthreads();

    // ---- gather 24-float window: conflict-free, lane-stride-1 LDS.128 ----
    float xv[24];
    {
        float4 a0 = sE[tid];        // l = 2*tid     -> sig[t0-8..t0-5]
        float4 a1 = sO[tid];        // l = 2*tid + 1
        float4 a2 = sE[tid + 1];
        float4 a3 = sO[tid + 1];
        float4 a4 = sE[tid + 2];
        float4 a5 = sO[tid + 2];
        xv[0]=a0.x;  xv[1]=a0.y;  xv[2]=a0.z;  xv[3]=a0.w;
        xv[4]=a1.x;  xv[5]=a1.y;  xv[6]=a1.z;  xv[7]=a1.w;
        xv[8]=a2.x;  xv[9]=a2.y;  xv[10]=a2.z; xv[11]=a2.w;
        xv[12]=a3.x; xv[13]=a3.y; xv[14]=a3.z; xv[15]=a3.w;
        xv[16]=a4.x; xv[17]=a4.y; xv[18]=a4.z; xv[19]=a4.w;
        xv[20]=a5.x; xv[21]=a5.y; xv[22]=a5.z; xv[23]=a5.w;
    }

    constexpr float H[10] = {
        0.160102397974125f,     0.6038292697974729f,
        0.7243085284385744f,    0.13842814590110342f,
       -0.24229488706619015f,  -0.03224486958502952f,
        0.07757149384006515f,  -0.006241490213011705f,
       -0.012580751999015526f,  0.003335725285001549f
    };

    // stage 1: 8 approximation coefficients
    float cA[8];
    #pragma unroll
    for (int r = 0; r < 8; r++) {
        float a = 0.0f;
        #pragma unroll
        for (int i = 0; i < 10; i++) {
            a = fmaf(H[i], xv[2*r + i], a);
        }
        cA[r] = a;
    }

    // stage 2: 8 outputs (4 even/odd pairs)
    float o[8];
    #pragma unroll
    for (int s = 0; s < 4; s++) {
        float e = 0.0f, od = 0.0f;
        #pragma unroll
        for (int rp = 0; rp < 5; rp++) {
            e  = fmaf(H[8 - 2*rp], cA[s + rp], e);
            od = fmaf(H[9 - 2*rp], cA[s + rp], od);
        }
        o[2*s + 0] = e;
        o[2*s + 1] = od;
    }

    float4* yo = reinterpret_cast<float4*>(y + rowbase) + F0 + 2 * tid;
    yo[0] = make_float4(o[0], o[1], o[2], o[3]);
    yo[1] = make_float4(o[4], o[5], o[6], o[7]);
}

extern "C" void kernel_launch(void* const* d_in, const int* in_sizes, int n_in,
                              void* d_out, int out_size)
{
    const float* x = (const float*)d_in[0];
    float* y = (float*)d_out;

    const int B = 64;
    const int total = in_sizes[0];            // 64 * 128 * 4096
    const int L = total / B;                  // 524288
    const int Lf4 = L / 4;                    // 131072
    const int blocksPerRow = Lf4 / TILE4;     // 256

    dim3 grid(blocksPerRow, B);
    wavelet_eo_kernel<<<grid, THREADS>>>(x, y, Lf4, blocksPerRow);
}